// round 14
// baseline (speedup 1.0000x reference)
#include <cuda_runtime.h>
#include <cuda_fp16.h>
#include <cstdint>

// ---------------- Problem constants ----------------
#define BATCH   8192
#define DH      1024
#define TILE_M  128             // batch rows per CTA
#define JBLK    32              // hidden cols per CTA (per gate)
#define KCH     64              // K elems per chunk (fp16: 128B rows)
#define NCHUNK  32              // 2*1024/64
#define THREADS 256

// ---------------- fp16 scratch (pre-rounded inputs), offsets in halfs ----------------
#define SCR_X 0u
#define SCR_H 8388608u
#define SCR_W 16777216u          // 8 matrices of 1048576 halfs: Wi,Wf,Wo,Wc,Ui,Uf,Uo,Uc
__device__ __half g_scrh[25165824];   // ~50.3 MB static scratch

// ---------------- SMEM layout ----------------
// [0,512)  bias (4 gates x 32 floats); [512,..) 3 stages x (A 16KB + B 16KB)
// epilogue: dump 128x132 floats at byte 512; c tile 16KB at byte 70144
#define SM_STAGE_B  512
#define A_BYTES     16384
#define STAGE_BYTES 32768
#define DUMP_PITCH  132
#define SM_C_BYTES  70144
#define SMEM_TOTAL  (512 + 3 * STAGE_BYTES)   // 98816 -> 2 CTAs/SM

// ---------------- helpers ----------------
__device__ __forceinline__ uint32_t smem_u32(const void* p) {
    uint32_t a;
    asm("{ .reg .u64 t; cvta.to.shared.u64 t, %1; cvt.u32.u64 %0, t; }" : "=r"(a) : "l"(p));
    return a;
}
__device__ __forceinline__ void mma_f16(float* d, const uint32_t* a, const uint32_t* b) {
    asm volatile(
        "mma.sync.aligned.m16n8k16.row.col.f32.f16.f16.f32 "
        "{%0,%1,%2,%3}, {%4,%5,%6,%7}, {%8,%9}, {%0,%1,%2,%3};"
        : "+f"(d[0]), "+f"(d[1]), "+f"(d[2]), "+f"(d[3])
        : "r"(a[0]), "r"(a[1]), "r"(a[2]), "r"(a[3]), "r"(b[0]), "r"(b[1]));
}
#define LDSM4(r, addr)                                                            \
    asm volatile("ldmatrix.sync.aligned.m8n8.x4.shared.b16 {%0,%1,%2,%3}, [%4];"  \
        : "=r"((r)[0]), "=r"((r)[1]), "=r"((r)[2]), "=r"((r)[3]) : "r"(addr))
#define CP_ASYNC16(dst, src) \
    asm volatile("cp.async.cg.shared.global [%0], [%1], 16;" :: "r"(dst), "l"(src))
#define CP_COMMIT()  asm volatile("cp.async.commit_group;" ::: "memory")
#define CP_WAIT(n)   asm volatile("cp.async.wait_group %0;" :: "n"(n) : "memory")

__device__ __forceinline__ float fast_sigmoid(float v) { return 1.0f / (1.0f + __expf(-v)); }
__device__ __forceinline__ float fast_tanh(float v) {
    return 1.0f - 2.0f / (__expf(2.0f * v) + 1.0f);   // exact +/-1 at large |v|
}

// ---------------- merged rounding pass (fp32 -> fp16 RN), one launch ----------------
// 24 regions of 1M floats, 256 blocks/region, 16 floats/thread, 2x16B stores.
__global__ void __launch_bounds__(256)
round_all_kernel(const float* __restrict__ x, const float* __restrict__ h,
                 const float* __restrict__ p0, const float* __restrict__ p1,
                 const float* __restrict__ p2, const float* __restrict__ p3,
                 const float* __restrict__ p4, const float* __restrict__ p5,
                 const float* __restrict__ p6, const float* __restrict__ p7) {
    const int r  = blockIdx.x >> 8;
    const int bi = blockIdx.x & 255;
    const size_t off = ((size_t)bi * 256 + threadIdx.x) * 16;
    const float* src;
    size_t dst;
    if (r < 8) {
        src = x + (((size_t)r) << 20) + off;
        dst = SCR_X + (((size_t)r) << 20) + off;
    } else if (r < 16) {
        src = h + (((size_t)(r - 8)) << 20) + off;
        dst = SCR_H + (((size_t)(r - 8)) << 20) + off;
    } else {
        const int g = r - 16;
        const float* wp = (g == 0) ? p0 : (g == 1) ? p1 : (g == 2) ? p2 : (g == 3) ? p3
                         : (g == 4) ? p4 : (g == 5) ? p5 : (g == 6) ? p6 : p7;
        src = wp + off;
        dst = SCR_W + (((size_t)g) << 20) + off;
    }
    float4 v0 = *(const float4*)src;
    float4 v1 = *(const float4*)(src + 4);
    float4 v2 = *(const float4*)(src + 8);
    float4 v3 = *(const float4*)(src + 12);
    __half2 a0 = __floats2half2_rn(v0.x, v0.y), a1 = __floats2half2_rn(v0.z, v0.w);
    __half2 a2 = __floats2half2_rn(v1.x, v1.y), a3 = __floats2half2_rn(v1.z, v1.w);
    __half2 a4 = __floats2half2_rn(v2.x, v2.y), a5 = __floats2half2_rn(v2.z, v2.w);
    __half2 a6 = __floats2half2_rn(v3.x, v3.y), a7 = __floats2half2_rn(v3.z, v3.w);
    uint4 w0 = { *(uint32_t*)&a0, *(uint32_t*)&a1, *(uint32_t*)&a2, *(uint32_t*)&a3 };
    uint4 w1 = { *(uint32_t*)&a4, *(uint32_t*)&a5, *(uint32_t*)&a6, *(uint32_t*)&a7 };
    *(uint4*)(g_scrh + dst) = w0;
    *(uint4*)(g_scrh + dst + 8) = w1;
}

// ---------------- stage producer (256 threads: 4 A + 4 B chunks each) ----------------
__device__ __forceinline__ void issue_stage(uint32_t st, int tt, uint32_t dA,
                                            const __half* gsA0, const __half* gsA1,
                                            const __half* gsB) {
    const int p = tt >> 4;               // 0: x/W, 1: h/U
    const int k = (tt & 15) * KCH;
    const __half* sa = (p ? gsA1 : gsA0) + k;
    const __half* sw = gsB + (size_t)p * 4194304 + k;
#pragma unroll
    for (int i = 0; i < 4; i++)          // A rows rA + 32*i (row stride 1024 halfs)
        CP_ASYNC16(st + dA + i * 4096, sa + (size_t)i * 32768);
#pragma unroll
    for (int g = 0; g < 4; g++)          // B rows g*32 + rA (gate-major)
        CP_ASYNC16(st + A_BYTES + dA + g * 4096, sw + (size_t)g * 1048576);
}

// ---------------- GEMM + fused LSTM kernel (champion core) ----------------
__global__ void __launch_bounds__(THREADS, 2)
lstm_mma11_kernel(const float* __restrict__ bi, const float* __restrict__ bfv,
                  const float* __restrict__ bo, const float* __restrict__ bc,
                  const float* __restrict__ c,
                  float* __restrict__ out_h, float* __restrict__ out_c) {
    extern __shared__ char smem[];
    float* smf = (float*)smem;
    const uint32_t sb = smem_u32(smem);

    const int tid  = threadIdx.x;
    const int wid  = tid >> 5;
    const int lane = tid & 31;
    const int warp_m = wid >> 2;      // 0..1 (64 rows each)
    const int warp_n = wid & 3;       // 0..3 (= gate, 32 cols each)
    const int j0 = blockIdx.x * JBLK;
    const int m0 = blockIdx.y * TILE_M;

    // bias -> smem [g*32 + jj]
    if (tid < 128) {
        const int g = tid >> 5, jj = tid & 31;
        const float* bp = (g == 0) ? bi : (g == 1) ? bfv : (g == 2) ? bo : bc;
        smf[tid] = bp[j0 + jj];
    }

    // -------- producer addressing (cp.async) --------
    const int rA  = tid >> 3;                 // 0..31
    const int seg = tid & 7;                  // 16B granule within 128B row
    const uint32_t dA = (uint32_t)(rA * 128 + ((seg ^ (rA & 7)) << 4));
    const __half* gsA0 = g_scrh + SCR_X + (size_t)(m0 + rA) * DH + seg * 8;
    const __half* gsA1 = g_scrh + SCR_H + (size_t)(m0 + rA) * DH + seg * 8;
    const __half* gsB  = g_scrh + SCR_W + (size_t)(j0 + rA) * DH + seg * 8;

    // -------- consumer (ldmatrix) addressing --------
    const uint32_t l7x = (uint32_t)((lane & 7) << 4);   // swizzle XOR term
    const uint32_t aoffb = (uint32_t)((warp_m * 64 + (lane & 15)) * 128);
    const uint32_t koffA = (uint32_t)((lane >> 4) << 4);
    const uint32_t boffb = (uint32_t)(A_BYTES +
                          (warp_n * 32 + (lane & 7) + (((lane >> 4) & 1) << 3)) * 128);
    const uint32_t koffB = (uint32_t)(((lane >> 3) & 1) << 4);

    float acc[4][4][4];
#pragma unroll
    for (int mi = 0; mi < 4; mi++)
#pragma unroll
        for (int ni = 0; ni < 4; ni++)
#pragma unroll
            for (int r = 0; r < 4; r++) acc[mi][ni][r] = 0.0f;

    // -------- prologue: stages 0,1 --------
    issue_stage(sb + SM_STAGE_B + 0 * STAGE_BYTES, 0, dA, gsA0, gsA1, gsB);
    CP_COMMIT();
    issue_stage(sb + SM_STAGE_B + 1 * STAGE_BYTES, 1, dA, gsA0, gsA1, gsB);
    CP_COMMIT();

    // -------- main loop --------
    int s = 0;   // compute buffer
    int u = 2;   // fill buffer
#pragma unroll 1
    for (int t = 0; t < NCHUNK; t++) {
        CP_WAIT(1);
        __syncthreads();
        if (t + 2 < NCHUNK) {
            issue_stage(sb + SM_STAGE_B + u * STAGE_BYTES, t + 2, dA, gsA0, gsA1, gsB);
        } else if (t == NCHUNK - 2) {
            // drain (moved one iter earlier than t=31): prefetch the c tile
            // (128 x 32 f32 = 16KB) into stage-2 bytes last read at t=29 — all
            // warps are past that compute via this iteration's __syncthreads.
            // Overlaps the c load with TWO chunks of remaining compute.
#pragma unroll
            for (int i = 0; i < 4; i++) {
                const int q = tid + i * THREADS;          // 0..1023 16B chunks
                const int row = q >> 3, c4 = q & 7;
                CP_ASYNC16(sb + SM_C_BYTES + q * 16,
                           c + (size_t)(m0 + row) * DH + j0 + c4 * 4);
            }
        }
        CP_COMMIT();

        const uint32_t st = sb + SM_STAGE_B + s * STAGE_BYTES;
        // warp-skewed k-subtile order (champion): spreads post-barrier LDSM bursts.
#pragma unroll
        for (int ks = 0; ks < 4; ks++) {
            const uint32_t kk = (uint32_t)((ks + wid) & 3);
            const uint32_t tA = (kk * 32 + koffA) ^ l7x;
            const uint32_t tB = (kk * 32 + koffB) ^ l7x;
            uint32_t a0[4], b0[4], b1[4];
            LDSM4(a0, st + aoffb + tA);           // mi 0 first: feeds 4 MMAs at once
            LDSM4(b0, st + boffb + tB);           // ni 0,1 (n0-15)
            LDSM4(b1, st + boffb + 2048 + tB);    // ni 2,3 (n16-31)
            mma_f16(acc[0][0], a0, b0 + 0);
            mma_f16(acc[0][1], a0, b0 + 2);
            mma_f16(acc[0][2], a0, b1 + 0);
            mma_f16(acc[0][3], a0, b1 + 2);
#pragma unroll
            for (int mi = 1; mi < 4; mi++) {
                uint32_t a[4];
                LDSM4(a, st + aoffb + mi * 2048 + tA);
                mma_f16(acc[mi][0], a, b0 + 0);
                mma_f16(acc[mi][1], a, b0 + 2);
                mma_f16(acc[mi][2], a, b1 + 0);
                mma_f16(acc[mi][3], a, b1 + 2);
            }
        }
        s = (s == 2) ? 0 : s + 1;
        u = (u == 2) ? 0 : u + 1;
    }
    CP_WAIT(0);
    __syncthreads();   // stages dead; dump may alias them; c tile landed

    // -------- dump accumulators to smem --------
    {
        float* dump = smf + 128;    // byte 512
        const int q  = lane >> 2;
        const int tg = lane & 3;
        const int dr = warp_m * 64 + q;
        const int dc = warp_n * 32 + tg * 2;
#pragma unroll
        for (int mi = 0; mi < 4; mi++)
#pragma unroll
            for (int ni = 0; ni < 4; ni++) {
                float2 v0 = { acc[mi][ni][0], acc[mi][ni][1] };
                float2 v1 = { acc[mi][ni][2], acc[mi][ni][3] };
                *(float2*)(dump + (dr + mi * 16) * DUMP_PITCH + dc + ni * 8) = v0;
                *(float2*)(dump + (dr + mi * 16 + 8) * DUMP_PITCH + dc + ni * 8) = v1;
            }
    }
    __syncthreads();

    // -------- fused LSTM epilogue --------
    {
        const float* dump = smf + 128;
        const float* bias = smf;
        const float* csm  = smf + SM_C_BYTES / 4;   // c tile, pitch 32 floats
        const int row8 = tid >> 3;
        const int jg = (tid & 7) * 4;
        const float4 bi4 = *(const float4*)(bias + jg);
        const float4 bf4 = *(const float4*)(bias + 32 + jg);
        const float4 bo4 = *(const float4*)(bias + 64 + jg);
        const float4 bc4 = *(const float4*)(bias + 96 + jg);
#pragma unroll
        for (int p = 0; p < 4; p++) {
            const int row = row8 + p * 32;
            const float4 gi = *(const float4*)(dump + row * DUMP_PITCH + jg);
            const float4 gf = *(const float4*)(dump + row * DUMP_PITCH + 32 + jg);
            const float4 go = *(const float4*)(dump + row * DUMP_PITCH + 64 + jg);
            const float4 gc = *(const float4*)(dump + row * DUMP_PITCH + 96 + jg);
            const float4 ci = *(const float4*)(csm + row * 32 + jg);
            const size_t o = (size_t)(m0 + row) * DH + j0 + jg;
            float4 nh, nc;
            {
                float ig = fast_sigmoid(gi.x + bi4.x), fg = fast_sigmoid(gf.x + bf4.x);
                float og = fast_sigmoid(go.x + bo4.x), cg = fast_tanh(gc.x + bc4.x);
                nc.x = fg * ci.x + ig * cg;  nh.x = og * fast_tanh(nc.x);
            }
            {
                float ig = fast_sigmoid(gi.y + bi4.y), fg = fast_sigmoid(gf.y + bf4.y);
                float og = fast_sigmoid(go.y + bo4.y), cg = fast_tanh(gc.y + bc4.y);
                nc.y = fg * ci.y + ig * cg;  nh.y = og * fast_tanh(nc.y);
            }
            {
                float ig = fast_sigmoid(gi.z + bi4.z), fg = fast_sigmoid(gf.z + bf4.z);
                float og = fast_sigmoid(go.z + bo4.z), cg = fast_tanh(gc.z + bc4.z);
                nc.z = fg * ci.z + ig * cg;  nh.z = og * fast_tanh(nc.z);
            }
            {
                float ig = fast_sigmoid(gi.w + bi4.w), fg = fast_sigmoid(gf.w + bf4.w);
                float og = fast_sigmoid(go.w + bo4.w), cg = fast_tanh(gc.w + bc4.w);
                nc.w = fg * ci.w + ig * cg;  nh.w = og * fast_tanh(nc.w);
            }
            *(float4*)(out_h + o) = nh;
            *(float4*)(out_c + o) = nc;
        }
    }
}

// ---------------- Host launch ----------------
extern "C" void kernel_launch(void* const* d_in, const int* in_sizes, int n_in,
                              void* d_out, int out_size) {
    const float* x  = (const float*)d_in[0];
    const float* h  = (const float*)d_in[1];
    const float* c  = (const float*)d_in[2];
    const float* Wi = (const float*)d_in[3];
    const float* bi = (const float*)d_in[4];
    const float* Ui = (const float*)d_in[5];
    const float* Wf = (const float*)d_in[6];
    const float* bf = (const float*)d_in[7];
    const float* Uf = (const float*)d_in[8];
    const float* Wo = (const float*)d_in[9];
    const float* bo = (const float*)d_in[10];
    const float* Uo = (const float*)d_in[11];
    const float* Wc = (const float*)d_in[12];
    const float* bc = (const float*)d_in[13];
    const float* Uc = (const float*)d_in[14];
    float* out_h = (float*)d_out;
    float* out_c = out_h + (size_t)BATCH * DH;

    static bool once = false;
    if (!once) {
        cudaFuncSetAttribute(lstm_mma11_kernel, cudaFuncAttributeMaxDynamicSharedMemorySize,
                             SMEM_TOTAL);
        once = true;
    }

    // 1) round all inputs to fp16 into scratch (single launch, 16 floats/thread)
    round_all_kernel<<<6144, 256>>>(x, h, Wi, Wf, Wo, Wc, Ui, Uf, Uo, Uc);

    // 2) GEMM + fused gates (champion configuration)
    dim3 grid(DH / JBLK, BATCH / TILE_M);   // (32, 64)
    lstm_mma11_kernel<<<grid, THREADS, SMEM_TOTAL>>>(bi, bf, bo, bc, c, out_h, out_c);
}

// round 15
// speedup vs baseline: 1.0280x; 1.0280x over previous
#include <cuda_runtime.h>
#include <cuda_fp16.h>
#include <cstdint>

// ---------------- Problem constants ----------------
#define BATCH   8192
#define DH      1024
#define TILE_M  128             // batch rows per CTA
#define JBLK    32              // hidden cols per CTA (per gate)
#define KCH     64              // K elems per chunk (fp16: 128B rows)
#define NCHUNK  32              // 2*1024/64
#define THREADS 256

// ---------------- fp16 scratch (pre-rounded inputs), offsets in halfs ----------------
#define SCR_X 0u
#define SCR_H 8388608u
#define SCR_W 16777216u          // 8 matrices of 1048576 halfs: Wi,Wf,Wo,Wc,Ui,Uf,Uo,Uc
__device__ __half g_scrh[25165824];   // ~50.3 MB static scratch

// ---------------- SMEM layout ----------------
// [0,512)  bias (4 gates x 32 floats); [512,..) 3 stages x (A 16KB + B 16KB)
// epilogue: dump 128x132 floats at byte 512; c tile 16KB at byte 70144
#define SM_STAGE_B  512
#define A_BYTES     16384
#define STAGE_BYTES 32768
#define DUMP_PITCH  132
#define SM_C_BYTES  70144
#define SMEM_TOTAL  (512 + 3 * STAGE_BYTES)   // 98816 -> 2 CTAs/SM

// ---------------- helpers ----------------
__device__ __forceinline__ uint32_t smem_u32(const void* p) {
    uint32_t a;
    asm("{ .reg .u64 t; cvta.to.shared.u64 t, %1; cvt.u32.u64 %0, t; }" : "=r"(a) : "l"(p));
    return a;
}
__device__ __forceinline__ void mma_f16(float* d, const uint32_t* a, const uint32_t* b) {
    asm volatile(
        "mma.sync.aligned.m16n8k16.row.col.f32.f16.f16.f32 "
        "{%0,%1,%2,%3}, {%4,%5,%6,%7}, {%8,%9}, {%0,%1,%2,%3};"
        : "+f"(d[0]), "+f"(d[1]), "+f"(d[2]), "+f"(d[3])
        : "r"(a[0]), "r"(a[1]), "r"(a[2]), "r"(a[3]), "r"(b[0]), "r"(b[1]));
}
#define LDSM4(r, addr)                                                            \
    asm volatile("ldmatrix.sync.aligned.m8n8.x4.shared.b16 {%0,%1,%2,%3}, [%4];"  \
        : "=r"((r)[0]), "=r"((r)[1]), "=r"((r)[2]), "=r"((r)[3]) : "r"(addr))
#define CP_ASYNC16(dst, src) \
    asm volatile("cp.async.cg.shared.global [%0], [%1], 16;" :: "r"(dst), "l"(src))
#define CP_COMMIT()  asm volatile("cp.async.commit_group;" ::: "memory")
#define CP_WAIT(n)   asm volatile("cp.async.wait_group %0;" :: "n"(n) : "memory")

__device__ __forceinline__ float fast_sigmoid(float v) { return 1.0f / (1.0f + __expf(-v)); }
__device__ __forceinline__ float fast_tanh(float v) {
    return 1.0f - 2.0f / (__expf(2.0f * v) + 1.0f);   // exact +/-1 at large |v|
}

// ---------------- merged rounding pass (fp32 -> fp16 RN), one launch ----------------
// 24 regions of 1M floats, 256 blocks/region, 16 floats/thread, 2x16B stores.
__global__ void __launch_bounds__(256)
round_all_kernel(const float* __restrict__ x, const float* __restrict__ h,
                 const float* __restrict__ p0, const float* __restrict__ p1,
                 const float* __restrict__ p2, const float* __restrict__ p3,
                 const float* __restrict__ p4, const float* __restrict__ p5,
                 const float* __restrict__ p6, const float* __restrict__ p7) {
    const int r  = blockIdx.x >> 8;
    const int bi = blockIdx.x & 255;
    const size_t off = ((size_t)bi * 256 + threadIdx.x) * 16;
    const float* src;
    size_t dst;
    if (r < 8) {
        src = x + (((size_t)r) << 20) + off;
        dst = SCR_X + (((size_t)r) << 20) + off;
    } else if (r < 16) {
        src = h + (((size_t)(r - 8)) << 20) + off;
        dst = SCR_H + (((size_t)(r - 8)) << 20) + off;
    } else {
        const int g = r - 16;
        const float* wp = (g == 0) ? p0 : (g == 1) ? p1 : (g == 2) ? p2 : (g == 3) ? p3
                         : (g == 4) ? p4 : (g == 5) ? p5 : (g == 6) ? p6 : p7;
        src = wp + off;
        dst = SCR_W + (((size_t)g) << 20) + off;
    }
    float4 v0 = *(const float4*)src;
    float4 v1 = *(const float4*)(src + 4);
    float4 v2 = *(const float4*)(src + 8);
    float4 v3 = *(const float4*)(src + 12);
    __half2 a0 = __floats2half2_rn(v0.x, v0.y), a1 = __floats2half2_rn(v0.z, v0.w);
    __half2 a2 = __floats2half2_rn(v1.x, v1.y), a3 = __floats2half2_rn(v1.z, v1.w);
    __half2 a4 = __floats2half2_rn(v2.x, v2.y), a5 = __floats2half2_rn(v2.z, v2.w);
    __half2 a6 = __floats2half2_rn(v3.x, v3.y), a7 = __floats2half2_rn(v3.z, v3.w);
    uint4 w0 = { *(uint32_t*)&a0, *(uint32_t*)&a1, *(uint32_t*)&a2, *(uint32_t*)&a3 };
    uint4 w1 = { *(uint32_t*)&a4, *(uint32_t*)&a5, *(uint32_t*)&a6, *(uint32_t*)&a7 };
    *(uint4*)(g_scrh + dst) = w0;
    *(uint4*)(g_scrh + dst + 8) = w1;
}

// ---------------- stage producer (256 threads: 4 A + 4 B chunks each) ----------------
__device__ __forceinline__ void issue_stage(uint32_t st, int tt, uint32_t dA,
                                            const __half* gsA0, const __half* gsA1,
                                            const __half* gsB) {
    const int p = tt >> 4;               // 0: x/W, 1: h/U
    const int k = (tt & 15) * KCH;
    const __half* sa = (p ? gsA1 : gsA0) + k;
    const __half* sw = gsB + (size_t)p * 4194304 + k;
#pragma unroll
    for (int i = 0; i < 4; i++)          // A rows rA + 32*i (row stride 1024 halfs)
        CP_ASYNC16(st + dA + i * 4096, sa + (size_t)i * 32768);
#pragma unroll
    for (int g = 0; g < 4; g++)          // B rows g*32 + rA (gate-major)
        CP_ASYNC16(st + A_BYTES + dA + g * 4096, sw + (size_t)g * 1048576);
}

// ---------------- GEMM + fused LSTM kernel (champion core, consumer-first) ------
__global__ void __launch_bounds__(THREADS, 2)
lstm_mma12_kernel(const float* __restrict__ bi, const float* __restrict__ bfv,
                  const float* __restrict__ bo, const float* __restrict__ bc,
                  const float* __restrict__ c,
                  float* __restrict__ out_h, float* __restrict__ out_c) {
    extern __shared__ char smem[];
    float* smf = (float*)smem;
    const uint32_t sb = smem_u32(smem);

    const int tid  = threadIdx.x;
    const int wid  = tid >> 5;
    const int lane = tid & 31;
    const int warp_m = wid >> 2;      // 0..1 (64 rows each)
    const int warp_n = wid & 3;       // 0..3 (= gate, 32 cols each)
    const int j0 = blockIdx.x * JBLK;
    const int m0 = blockIdx.y * TILE_M;

    // bias -> smem [g*32 + jj]
    if (tid < 128) {
        const int g = tid >> 5, jj = tid & 31;
        const float* bp = (g == 0) ? bi : (g == 1) ? bfv : (g == 2) ? bo : bc;
        smf[tid] = bp[j0 + jj];
    }

    // -------- producer addressing (cp.async) --------
    const int rA  = tid >> 3;                 // 0..31
    const int seg = tid & 7;                  // 16B granule within 128B row
    const uint32_t dA = (uint32_t)(rA * 128 + ((seg ^ (rA & 7)) << 4));
    const __half* gsA0 = g_scrh + SCR_X + (size_t)(m0 + rA) * DH + seg * 8;
    const __half* gsA1 = g_scrh + SCR_H + (size_t)(m0 + rA) * DH + seg * 8;
    const __half* gsB  = g_scrh + SCR_W + (size_t)(j0 + rA) * DH + seg * 8;

    // -------- consumer (ldmatrix) addressing --------
    const uint32_t l7x = (uint32_t)((lane & 7) << 4);   // swizzle XOR term
    const uint32_t aoffb = (uint32_t)((warp_m * 64 + (lane & 15)) * 128);
    const uint32_t koffA = (uint32_t)((lane >> 4) << 4);
    const uint32_t boffb = (uint32_t)(A_BYTES +
                          (warp_n * 32 + (lane & 7) + (((lane >> 4) & 1) << 3)) * 128);
    const uint32_t koffB = (uint32_t)(((lane >> 3) & 1) << 4);

    float acc[4][4][4];
#pragma unroll
    for (int mi = 0; mi < 4; mi++)
#pragma unroll
        for (int ni = 0; ni < 4; ni++)
#pragma unroll
            for (int r = 0; r < 4; r++) acc[mi][ni][r] = 0.0f;

    // -------- prologue: stages 0,1 --------
    issue_stage(sb + SM_STAGE_B + 0 * STAGE_BYTES, 0, dA, gsA0, gsA1, gsB);
    CP_COMMIT();
    issue_stage(sb + SM_STAGE_B + 1 * STAGE_BYTES, 1, dA, gsA0, gsA1, gsB);
    CP_COMMIT();

    // -------- main loop: consumer-first chunk schedule --------
    int s = 0;   // compute buffer
    int u = 2;   // fill buffer
#pragma unroll 1
    for (int t = 0; t < NCHUNK; t++) {
        CP_WAIT(1);
        __syncthreads();

        const uint32_t st = sb + SM_STAGE_B + s * STAGE_BYTES;

        // ---- ks=0 block FIRST: tensor pipe starts immediately post-barrier ----
        {
            const uint32_t kk = (uint32_t)(wid & 3);          // skewed ks=0
            const uint32_t tA = (kk * 32 + koffA) ^ l7x;
            const uint32_t tB = (kk * 32 + koffB) ^ l7x;
            uint32_t b0[4], b1[4];
            LDSM4(b0, st + boffb + tB);
            LDSM4(b1, st + boffb + 2048 + tB);
#pragma unroll
            for (int mi = 0; mi < 4; mi++) {
                uint32_t a[4];
                LDSM4(a, st + aoffb + mi * 2048 + tA);
                mma_f16(acc[mi][0], a, b0 + 0);
                mma_f16(acc[mi][1], a, b0 + 2);
                mma_f16(acc[mi][2], a, b1 + 0);
                mma_f16(acc[mi][3], a, b1 + 2);
            }
        }

        // ---- producer work (address math + cp.asyncs) between ks=0 and ks=1 ----
        if (t + 2 < NCHUNK) {
            issue_stage(sb + SM_STAGE_B + u * STAGE_BYTES, t + 2, dA, gsA0, gsA1, gsB);
        } else if (t == NCHUNK - 1) {
            // drain: prefetch the c tile (128 x 32 f32 = 16KB) into free smem.
#pragma unroll
            for (int i = 0; i < 4; i++) {
                const int q = tid + i * THREADS;          // 0..1023 16B chunks
                const int row = q >> 3, c4 = q & 7;
                CP_ASYNC16(sb + SM_C_BYTES + q * 16,
                           c + (size_t)(m0 + row) * DH + j0 + c4 * 4);
            }
        }
        CP_COMMIT();

        // ---- remaining ks blocks ----
#pragma unroll
        for (int ks = 1; ks < 4; ks++) {
            const uint32_t kk = (uint32_t)((ks + wid) & 3);
            const uint32_t tA = (kk * 32 + koffA) ^ l7x;
            const uint32_t tB = (kk * 32 + koffB) ^ l7x;
            uint32_t b0[4], b1[4];
            LDSM4(b0, st + boffb + tB);
            LDSM4(b1, st + boffb + 2048 + tB);
#pragma unroll
            for (int mi = 0; mi < 4; mi++) {
                uint32_t a[4];
                LDSM4(a, st + aoffb + mi * 2048 + tA);
                mma_f16(acc[mi][0], a, b0 + 0);
                mma_f16(acc[mi][1], a, b0 + 2);
                mma_f16(acc[mi][2], a, b1 + 0);
                mma_f16(acc[mi][3], a, b1 + 2);
            }
        }
        s = (s == 2) ? 0 : s + 1;
        u = (u == 2) ? 0 : u + 1;
    }
    CP_WAIT(0);
    __syncthreads();   // stages dead; dump may alias them; c tile landed

    // -------- dump accumulators to smem --------
    {
        float* dump = smf + 128;    // byte 512
        const int q  = lane >> 2;
        const int tg = lane & 3;
        const int dr = warp_m * 64 + q;
        const int dc = warp_n * 32 + tg * 2;
#pragma unroll
        for (int mi = 0; mi < 4; mi++)
#pragma unroll
            for (int ni = 0; ni < 4; ni++) {
                float2 v0 = { acc[mi][ni][0], acc[mi][ni][1] };
                float2 v1 = { acc[mi][ni][2], acc[mi][ni][3] };
                *(float2*)(dump + (dr + mi * 16) * DUMP_PITCH + dc + ni * 8) = v0;
                *(float2*)(dump + (dr + mi * 16 + 8) * DUMP_PITCH + dc + ni * 8) = v1;
            }
    }
    __syncthreads();

    // -------- fused LSTM epilogue --------
    {
        const float* dump = smf + 128;
        const float* bias = smf;
        const float* csm  = smf + SM_C_BYTES / 4;   // c tile, pitch 32 floats
        const int row8 = tid >> 3;
        const int jg = (tid & 7) * 4;
        const float4 bi4 = *(const float4*)(bias + jg);
        const float4 bf4 = *(const float4*)(bias + 32 + jg);
        const float4 bo4 = *(const float4*)(bias + 64 + jg);
        const float4 bc4 = *(const float4*)(bias + 96 + jg);
#pragma unroll
        for (int p = 0; p < 4; p++) {
            const int row = row8 + p * 32;
            const float4 gi = *(const float4*)(dump + row * DUMP_PITCH + jg);
            const float4 gf = *(const float4*)(dump + row * DUMP_PITCH + 32 + jg);
            const float4 go = *(const float4*)(dump + row * DUMP_PITCH + 64 + jg);
            const float4 gc = *(const float4*)(dump + row * DUMP_PITCH + 96 + jg);
            const float4 ci = *(const float4*)(csm + row * 32 + jg);
            const size_t o = (size_t)(m0 + row) * DH + j0 + jg;
            float4 nh, nc;
            {
                float ig = fast_sigmoid(gi.x + bi4.x), fg = fast_sigmoid(gf.x + bf4.x);
                float og = fast_sigmoid(go.x + bo4.x), cg = fast_tanh(gc.x + bc4.x);
                nc.x = fg * ci.x + ig * cg;  nh.x = og * fast_tanh(nc.x);
            }
            {
                float ig = fast_sigmoid(gi.y + bi4.y), fg = fast_sigmoid(gf.y + bf4.y);
                float og = fast_sigmoid(go.y + bo4.y), cg = fast_tanh(gc.y + bc4.y);
                nc.y = fg * ci.y + ig * cg;  nh.y = og * fast_tanh(nc.y);
            }
            {
                float ig = fast_sigmoid(gi.z + bi4.z), fg = fast_sigmoid(gf.z + bf4.z);
                float og = fast_sigmoid(go.z + bo4.z), cg = fast_tanh(gc.z + bc4.z);
                nc.z = fg * ci.z + ig * cg;  nh.z = og * fast_tanh(nc.z);
            }
            {
                float ig = fast_sigmoid(gi.w + bi4.w), fg = fast_sigmoid(gf.w + bf4.w);
                float og = fast_sigmoid(go.w + bo4.w), cg = fast_tanh(gc.w + bc4.w);
                nc.w = fg * ci.w + ig * cg;  nh.w = og * fast_tanh(nc.w);
            }
            *(float4*)(out_h + o) = nh;
            *(float4*)(out_c + o) = nc;
        }
    }
}

// ---------------- Host launch ----------------
extern "C" void kernel_launch(void* const* d_in, const int* in_sizes, int n_in,
                              void* d_out, int out_size) {
    const float* x  = (const float*)d_in[0];
    const float* h  = (const float*)d_in[1];
    const float* c  = (const float*)d_in[2];
    const float* Wi = (const float*)d_in[3];
    const float* bi = (const float*)d_in[4];
    const float* Ui = (const float*)d_in[5];
    const float* Wf = (const float*)d_in[6];
    const float* bf = (const float*)d_in[7];
    const float* Uf = (const float*)d_in[8];
    const float* Wo = (const float*)d_in[9];
    const float* bo = (const float*)d_in[10];
    const float* Uo = (const float*)d_in[11];
    const float* Wc = (const float*)d_in[12];
    const float* bc = (const float*)d_in[13];
    const float* Uc = (const float*)d_in[14];
    float* out_h = (float*)d_out;
    float* out_c = out_h + (size_t)BATCH * DH;

    static bool once = false;
    if (!once) {
        cudaFuncSetAttribute(lstm_mma12_kernel, cudaFuncAttributeMaxDynamicSharedMemorySize,
                             SMEM_TOTAL);
        once = true;
    }

    // 1) round all inputs to fp16 into scratch (single launch, 16 floats/thread)
    round_all_kernel<<<6144, 256>>>(x, h, Wi, Wf, Wo, Wc, Ui, Uf, Uo, Uc);

    // 2) GEMM + fused gates (champion configuration, consumer-first schedule)
    dim3 grid(DH / JBLK, BATCH / TILE_M);   // (32, 64)
    lstm_mma12_kernel<<<grid, THREADS, SMEM_TOTAL>>>(bi, bf, bo, bc, c, out_h, out_c);
}

// round 16
// speedup vs baseline: 1.0318x; 1.0038x over previous
#include <cuda_runtime.h>
#include <cuda_fp16.h>
#include <cstdint>

// ---------------- Problem constants ----------------
#define BATCH   8192
#define DH      1024
#define TILE_M  128             // batch rows per CTA
#define JBLK    32              // hidden cols per CTA (per gate)
#define KCH     64              // K elems per chunk (fp16: 128B rows)
#define NCHUNK  32              // 2*1024/64
#define THREADS 256

// ---------------- fp16 scratch (pre-rounded inputs), offsets in halfs ----------------
#define SCR_X 0u
#define SCR_H 8388608u
#define SCR_W 16777216u          // 8 matrices of 1048576 halfs: Wi,Wf,Wo,Wc,Ui,Uf,Uo,Uc
__device__ __half g_scrh[25165824];   // ~50.3 MB static scratch

// ---------------- SMEM layout ----------------
// [0,512)  bias (4 gates x 32 floats); [512,..) 3 stages x (A 16KB + B 16KB)
// epilogue: dump 128x132 floats at byte 512; c tile 16KB at byte 70144
#define SM_STAGE_B  512
#define A_BYTES     16384
#define STAGE_BYTES 32768
#define DUMP_PITCH  132
#define SM_C_BYTES  70144
#define SMEM_TOTAL  (512 + 3 * STAGE_BYTES)   // 98816 -> 2 CTAs/SM

// ---------------- helpers ----------------
__device__ __forceinline__ uint32_t smem_u32(const void* p) {
    uint32_t a;
    asm("{ .reg .u64 t; cvta.to.shared.u64 t, %1; cvt.u32.u64 %0, t; }" : "=r"(a) : "l"(p));
    return a;
}
__device__ __forceinline__ void mma_f16(float* d, const uint32_t* a, const uint32_t* b) {
    asm volatile(
        "mma.sync.aligned.m16n8k16.row.col.f32.f16.f16.f32 "
        "{%0,%1,%2,%3}, {%4,%5,%6,%7}, {%8,%9}, {%0,%1,%2,%3};"
        : "+f"(d[0]), "+f"(d[1]), "+f"(d[2]), "+f"(d[3])
        : "r"(a[0]), "r"(a[1]), "r"(a[2]), "r"(a[3]), "r"(b[0]), "r"(b[1]));
}
#define LDSM4(r, addr)                                                            \
    asm volatile("ldmatrix.sync.aligned.m8n8.x4.shared.b16 {%0,%1,%2,%3}, [%4];"  \
        : "=r"((r)[0]), "=r"((r)[1]), "=r"((r)[2]), "=r"((r)[3]) : "r"(addr))
#define CP_ASYNC16(dst, src) \
    asm volatile("cp.async.cg.shared.global [%0], [%1], 16;" :: "r"(dst), "l"(src))
#define CP_COMMIT()  asm volatile("cp.async.commit_group;" ::: "memory")
#define CP_WAIT(n)   asm volatile("cp.async.wait_group %0;" :: "n"(n) : "memory")

__device__ __forceinline__ float fast_sigmoid(float v) { return 1.0f / (1.0f + __expf(-v)); }
__device__ __forceinline__ float fast_tanh(float v) {
    return 1.0f - 2.0f / (__expf(2.0f * v) + 1.0f);   // exact +/-1 at large |v|
}

// ---------------- merged rounding pass (fp32 -> fp16 RN), one launch ----------------
// 24 regions of 1M floats, 256 blocks/region, 16 floats/thread, 2x16B stores.
__global__ void __launch_bounds__(256)
round_all_kernel(const float* __restrict__ x, const float* __restrict__ h,
                 const float* __restrict__ p0, const float* __restrict__ p1,
                 const float* __restrict__ p2, const float* __restrict__ p3,
                 const float* __restrict__ p4, const float* __restrict__ p5,
                 const float* __restrict__ p6, const float* __restrict__ p7) {
    const int r  = blockIdx.x >> 8;
    const int bi = blockIdx.x & 255;
    const size_t off = ((size_t)bi * 256 + threadIdx.x) * 16;
    const float* src;
    size_t dst;
    if (r < 8) {
        src = x + (((size_t)r) << 20) + off;
        dst = SCR_X + (((size_t)r) << 20) + off;
    } else if (r < 16) {
        src = h + (((size_t)(r - 8)) << 20) + off;
        dst = SCR_H + (((size_t)(r - 8)) << 20) + off;
    } else {
        const int g = r - 16;
        const float* wp = (g == 0) ? p0 : (g == 1) ? p1 : (g == 2) ? p2 : (g == 3) ? p3
                         : (g == 4) ? p4 : (g == 5) ? p5 : (g == 6) ? p6 : p7;
        src = wp + off;
        dst = SCR_W + (((size_t)g) << 20) + off;
    }
    float4 v0 = *(const float4*)src;
    float4 v1 = *(const float4*)(src + 4);
    float4 v2 = *(const float4*)(src + 8);
    float4 v3 = *(const float4*)(src + 12);
    __half2 a0 = __floats2half2_rn(v0.x, v0.y), a1 = __floats2half2_rn(v0.z, v0.w);
    __half2 a2 = __floats2half2_rn(v1.x, v1.y), a3 = __floats2half2_rn(v1.z, v1.w);
    __half2 a4 = __floats2half2_rn(v2.x, v2.y), a5 = __floats2half2_rn(v2.z, v2.w);
    __half2 a6 = __floats2half2_rn(v3.x, v3.y), a7 = __floats2half2_rn(v3.z, v3.w);
    uint4 w0 = { *(uint32_t*)&a0, *(uint32_t*)&a1, *(uint32_t*)&a2, *(uint32_t*)&a3 };
    uint4 w1 = { *(uint32_t*)&a4, *(uint32_t*)&a5, *(uint32_t*)&a6, *(uint32_t*)&a7 };
    *(uint4*)(g_scrh + dst) = w0;
    *(uint4*)(g_scrh + dst + 8) = w1;
}

// ---------------- split stage producers: A half and B half ----------------
__device__ __forceinline__ void issue_stage_a(uint32_t st, int tt, uint32_t dA,
                                              const __half* gsA0, const __half* gsA1) {
    const int p = tt >> 4;               // 0: x, 1: h
    const int k = (tt & 15) * KCH;
    const __half* sa = (p ? gsA1 : gsA0) + k;
#pragma unroll
    for (int i = 0; i < 4; i++)          // A rows rA + 32*i (row stride 1024 halfs)
        CP_ASYNC16(st + dA + i * 4096, sa + (size_t)i * 32768);
}
__device__ __forceinline__ void issue_stage_b(uint32_t st, int tt, uint32_t dA,
                                              const __half* gsB) {
    const int p = tt >> 4;               // 0: W, 1: U
    const int k = (tt & 15) * KCH;
    const __half* sw = gsB + (size_t)p * 4194304 + k;
#pragma unroll
    for (int g = 0; g < 4; g++)          // B rows g*32 + rA (gate-major)
        CP_ASYNC16(st + A_BYTES + dA + g * 4096, sw + (size_t)g * 1048576);
}

// ---------------- GEMM + fused LSTM kernel (consumer-first, split producer) -----
__global__ void __launch_bounds__(THREADS, 2)
lstm_mma13_kernel(const float* __restrict__ bi, const float* __restrict__ bfv,
                  const float* __restrict__ bo, const float* __restrict__ bc,
                  const float* __restrict__ c,
                  float* __restrict__ out_h, float* __restrict__ out_c) {
    extern __shared__ char smem[];
    float* smf = (float*)smem;
    const uint32_t sb = smem_u32(smem);

    const int tid  = threadIdx.x;
    const int wid  = tid >> 5;
    const int lane = tid & 31;
    const int warp_m = wid >> 2;      // 0..1 (64 rows each)
    const int warp_n = wid & 3;       // 0..3 (= gate, 32 cols each)
    const int j0 = blockIdx.x * JBLK;
    const int m0 = blockIdx.y * TILE_M;

    // bias -> smem [g*32 + jj]
    if (tid < 128) {
        const int g = tid >> 5, jj = tid & 31;
        const float* bp = (g == 0) ? bi : (g == 1) ? bfv : (g == 2) ? bo : bc;
        smf[tid] = bp[j0 + jj];
    }

    // -------- producer addressing (cp.async) --------
    const int rA  = tid >> 3;                 // 0..31
    const int seg = tid & 7;                  // 16B granule within 128B row
    const uint32_t dA = (uint32_t)(rA * 128 + ((seg ^ (rA & 7)) << 4));
    const __half* gsA0 = g_scrh + SCR_X + (size_t)(m0 + rA) * DH + seg * 8;
    const __half* gsA1 = g_scrh + SCR_H + (size_t)(m0 + rA) * DH + seg * 8;
    const __half* gsB  = g_scrh + SCR_W + (size_t)(j0 + rA) * DH + seg * 8;

    // -------- consumer (ldmatrix) addressing --------
    const uint32_t l7x = (uint32_t)((lane & 7) << 4);   // swizzle XOR term
    const uint32_t aoffb = (uint32_t)((warp_m * 64 + (lane & 15)) * 128);
    const uint32_t koffA = (uint32_t)((lane >> 4) << 4);
    const uint32_t boffb = (uint32_t)(A_BYTES +
                          (warp_n * 32 + (lane & 7) + (((lane >> 4) & 1) << 3)) * 128);
    const uint32_t koffB = (uint32_t)(((lane >> 3) & 1) << 4);

    float acc[4][4][4];
#pragma unroll
    for (int mi = 0; mi < 4; mi++)
#pragma unroll
        for (int ni = 0; ni < 4; ni++)
#pragma unroll
            for (int r = 0; r < 4; r++) acc[mi][ni][r] = 0.0f;

    // -------- prologue: stages 0,1 --------
    issue_stage_a(sb + SM_STAGE_B + 0 * STAGE_BYTES, 0, dA, gsA0, gsA1);
    issue_stage_b(sb + SM_STAGE_B + 0 * STAGE_BYTES, 0, dA, gsB);
    CP_COMMIT();
    issue_stage_a(sb + SM_STAGE_B + 1 * STAGE_BYTES, 1, dA, gsA0, gsA1);
    issue_stage_b(sb + SM_STAGE_B + 1 * STAGE_BYTES, 1, dA, gsB);
    CP_COMMIT();

    // -------- main loop: consumer-first, producer split across two ks gaps -----
    int s = 0;   // compute buffer
    int u = 2;   // fill buffer
#pragma unroll 1
    for (int t = 0; t < NCHUNK; t++) {
        CP_WAIT(1);
        __syncthreads();

        const uint32_t st  = sb + SM_STAGE_B + s * STAGE_BYTES;
        const uint32_t stu = sb + SM_STAGE_B + u * STAGE_BYTES;
        const bool fill = (t + 2 < NCHUNK);

        // ---- ks=0 block FIRST: tensor pipe starts immediately post-barrier ----
        {
            const uint32_t kk = (uint32_t)(wid & 3);
            const uint32_t tA = (kk * 32 + koffA) ^ l7x;
            const uint32_t tB = (kk * 32 + koffB) ^ l7x;
            uint32_t b0[4], b1[4];
            LDSM4(b0, st + boffb + tB);
            LDSM4(b1, st + boffb + 2048 + tB);
#pragma unroll
            for (int mi = 0; mi < 4; mi++) {
                uint32_t a[4];
                LDSM4(a, st + aoffb + mi * 2048 + tA);
                mma_f16(acc[mi][0], a, b0 + 0);
                mma_f16(acc[mi][1], a, b0 + 2);
                mma_f16(acc[mi][2], a, b1 + 0);
                mma_f16(acc[mi][3], a, b1 + 2);
            }
        }

        // ---- producer A-half between ks=0 and ks=1 ----
        if (fill) issue_stage_a(stu, t + 2, dA, gsA0, gsA1);

        // ---- ks=1 block ----
        {
            const uint32_t kk = (uint32_t)((1 + wid) & 3);
            const uint32_t tA = (kk * 32 + koffA) ^ l7x;
            const uint32_t tB = (kk * 32 + koffB) ^ l7x;
            uint32_t b0[4], b1[4];
            LDSM4(b0, st + boffb + tB);
            LDSM4(b1, st + boffb + 2048 + tB);
#pragma unroll
            for (int mi = 0; mi < 4; mi++) {
                uint32_t a[4];
                LDSM4(a, st + aoffb + mi * 2048 + tA);
                mma_f16(acc[mi][0], a, b0 + 0);
                mma_f16(acc[mi][1], a, b0 + 2);
                mma_f16(acc[mi][2], a, b1 + 0);
                mma_f16(acc[mi][3], a, b1 + 2);
            }
        }

        // ---- producer B-half (+ drain c-prefetch) between ks=1 and ks=2 ----
        if (fill) {
            issue_stage_b(stu, t + 2, dA, gsB);
        } else if (t == NCHUNK - 1) {
            // drain: prefetch the c tile (128 x 32 f32 = 16KB) into free smem.
#pragma unroll
            for (int i = 0; i < 4; i++) {
                const int q = tid + i * THREADS;          // 0..1023 16B chunks
                const int row = q >> 3, c4 = q & 7;
                CP_ASYNC16(sb + SM_C_BYTES + q * 16,
                           c + (size_t)(m0 + row) * DH + j0 + c4 * 4);
            }
        }
        CP_COMMIT();   // exactly one commit group per iteration (semantics unchanged)

        // ---- ks=2,3 blocks ----
#pragma unroll
        for (int ks = 2; ks < 4; ks++) {
            const uint32_t kk = (uint32_t)((ks + wid) & 3);
            const uint32_t tA = (kk * 32 + koffA) ^ l7x;
            const uint32_t tB = (kk * 32 + koffB) ^ l7x;
            uint32_t b0[4], b1[4];
            LDSM4(b0, st + boffb + tB);
            LDSM4(b1, st + boffb + 2048 + tB);
#pragma unroll
            for (int mi = 0; mi < 4; mi++) {
                uint32_t a[4];
                LDSM4(a, st + aoffb + mi * 2048 + tA);
                mma_f16(acc[mi][0], a, b0 + 0);
                mma_f16(acc[mi][1], a, b0 + 2);
                mma_f16(acc[mi][2], a, b1 + 0);
                mma_f16(acc[mi][3], a, b1 + 2);
            }
        }
        s = (s == 2) ? 0 : s + 1;
        u = (u == 2) ? 0 : u + 1;
    }
    CP_WAIT(0);
    __syncthreads();   // stages dead; dump may alias them; c tile landed

    // -------- dump accumulators to smem --------
    {
        float* dump = smf + 128;    // byte 512
        const int q  = lane >> 2;
        const int tg = lane & 3;
        const int dr = warp_m * 64 + q;
        const int dc = warp_n * 32 + tg * 2;
#pragma unroll
        for (int mi = 0; mi < 4; mi++)
#pragma unroll
            for (int ni = 0; ni < 4; ni++) {
                float2 v0 = { acc[mi][ni][0], acc[mi][ni][1] };
                float2 v1 = { acc[mi][ni][2], acc[mi][ni][3] };
                *(float2*)(dump + (dr + mi * 16) * DUMP_PITCH + dc + ni * 8) = v0;
                *(float2*)(dump + (dr + mi * 16 + 8) * DUMP_PITCH + dc + ni * 8) = v1;
            }
    }
    __syncthreads();

    // -------- fused LSTM epilogue --------
    {
        const float* dump = smf + 128;
        const float* bias = smf;
        const float* csm  = smf + SM_C_BYTES / 4;   // c tile, pitch 32 floats
        const int row8 = tid >> 3;
        const int jg = (tid & 7) * 4;
        const float4 bi4 = *(const float4*)(bias + jg);
        const float4 bf4 = *(const float4*)(bias + 32 + jg);
        const float4 bo4 = *(const float4*)(bias + 64 + jg);
        const float4 bc4 = *(const float4*)(bias + 96 + jg);
#pragma unroll
        for (int p = 0; p < 4; p++) {
            const int row = row8 + p * 32;
            const float4 gi = *(const float4*)(dump + row * DUMP_PITCH + jg);
            const float4 gf = *(const float4*)(dump + row * DUMP_PITCH + 32 + jg);
            const float4 go = *(const float4*)(dump + row * DUMP_PITCH + 64 + jg);
            const float4 gc = *(const float4*)(dump + row * DUMP_PITCH + 96 + jg);
            const float4 ci = *(const float4*)(csm + row * 32 + jg);
            const size_t o = (size_t)(m0 + row) * DH + j0 + jg;
            float4 nh, nc;
            {
                float ig = fast_sigmoid(gi.x + bi4.x), fg = fast_sigmoid(gf.x + bf4.x);
                float og = fast_sigmoid(go.x + bo4.x), cg = fast_tanh(gc.x + bc4.x);
                nc.x = fg * ci.x + ig * cg;  nh.x = og * fast_tanh(nc.x);
            }
            {
                float ig = fast_sigmoid(gi.y + bi4.y), fg = fast_sigmoid(gf.y + bf4.y);
                float og = fast_sigmoid(go.y + bo4.y), cg = fast_tanh(gc.y + bc4.y);
                nc.y = fg * ci.y + ig * cg;  nh.y = og * fast_tanh(nc.y);
            }
            {
                float ig = fast_sigmoid(gi.z + bi4.z), fg = fast_sigmoid(gf.z + bf4.z);
                float og = fast_sigmoid(go.z + bo4.z), cg = fast_tanh(gc.z + bc4.z);
                nc.z = fg * ci.z + ig * cg;  nh.z = og * fast_tanh(nc.z);
            }
            {
                float ig = fast_sigmoid(gi.w + bi4.w), fg = fast_sigmoid(gf.w + bf4.w);
                float og = fast_sigmoid(go.w + bo4.w), cg = fast_tanh(gc.w + bc4.w);
                nc.w = fg * ci.w + ig * cg;  nh.w = og * fast_tanh(nc.w);
            }
            *(float4*)(out_h + o) = nh;
            *(float4*)(out_c + o) = nc;
        }
    }
}

// ---------------- Host launch ----------------
extern "C" void kernel_launch(void* const* d_in, const int* in_sizes, int n_in,
                              void* d_out, int out_size) {
    const float* x  = (const float*)d_in[0];
    const float* h  = (const float*)d_in[1];
    const float* c  = (const float*)d_in[2];
    const float* Wi = (const float*)d_in[3];
    const float* bi = (const float*)d_in[4];
    const float* Ui = (const float*)d_in[5];
    const float* Wf = (const float*)d_in[6];
    const float* bf = (const float*)d_in[7];
    const float* Uf = (const float*)d_in[8];
    const float* Wo = (const float*)d_in[9];
    const float* bo = (const float*)d_in[10];
    const float* Uo = (const float*)d_in[11];
    const float* Wc = (const float*)d_in[12];
    const float* bc = (const float*)d_in[13];
    const float* Uc = (const float*)d_in[14];
    float* out_h = (float*)d_out;
    float* out_c = out_h + (size_t)BATCH * DH;

    static bool once = false;
    if (!once) {
        cudaFuncSetAttribute(lstm_mma13_kernel, cudaFuncAttributeMaxDynamicSharedMemorySize,
                             SMEM_TOTAL);
        once = true;
    }

    // 1) round all inputs to fp16 into scratch (single launch, 16 floats/thread)
    round_all_kernel<<<6144, 256>>>(x, h, Wi, Wf, Wo, Wc, Ui, Uf, Uo, Uc);

    // 2) GEMM + fused gates (consumer-first, split producer)
    dim3 grid(DH / JBLK, BATCH / TILE_M);   // (32, 64)
    lstm_mma13_kernel<<<grid, THREADS, SMEM_TOTAL>>>(bi, bf, bo, bc, c, out_h, out_c);
}